// round 7
// baseline (speedup 1.0000x reference)
#include <cuda_runtime.h>

// out[b,c] = dot(x[b,c,:HW], weight[c,:HW]) + bias[c]
// B = 512, C = 512, HW = 784 (float32). HBM-streaming bound (~828 MB total
// DRAM traffic, already minimal). CTA-granularity axis has paid twice
// (256->128->64 thr: 123.4 -> 119.3 -> 117.2 us). R7 = endpoint of the axis:
// one warp per CTA (32 threads, 262144 blocks). 32 warps/SM resident still
// holds ~112 KB of in-flight loads per SM vs ~16 KB needed -> DRAM stays fed.

#define B_DIM 512
#define C_DIM 512
#define HW_DIM 784
#define HW_VEC4 (HW_DIM / 4)        // 196 float4 per row
#define TOTAL_ROWS (B_DIM * C_DIM)  // 262144

__global__ __launch_bounds__(32) void scalar_mapping_kernel(
    const float* __restrict__ x,
    const float* __restrict__ weight,
    const float* __restrict__ bias,
    float* __restrict__ out)
{
    const int warp = blockIdx.x;           // row = b*C + c
    const int lane = threadIdx.x;          // 0..31

    const int c = warp & (C_DIM - 1);

    const float4* __restrict__ xr =
        reinterpret_cast<const float4*>(x + (size_t)warp * HW_DIM);
    const float4* __restrict__ wr =
        reinterpret_cast<const float4*>(weight + (size_t)c * HW_DIM);

    float sum = 0.0f;

    // 196 float4 per row; 6 full warp-iterations + 1 partial (lanes 0-3).
    #pragma unroll
    for (int i = 0; i < 7; ++i) {
        const int idx = lane + i * 32;
        if (idx < HW_VEC4) {
            const float4 xv = __ldcs(&xr[idx]);  // x streamed once, evict-first
            const float4 wv = __ldg(&wr[idx]);   // weight stays L2-resident
            sum = fmaf(xv.x, wv.x, sum);
            sum = fmaf(xv.y, wv.y, sum);
            sum = fmaf(xv.z, wv.z, sum);
            sum = fmaf(xv.w, wv.w, sum);
        }
    }

    // Warp butterfly reduce
    #pragma unroll
    for (int off = 16; off > 0; off >>= 1)
        sum += __shfl_xor_sync(0xFFFFFFFFu, sum, off);

    if (lane == 0)
        out[warp] = sum + __ldg(&bias[c]);
}

extern "C" void kernel_launch(void* const* d_in, const int* in_sizes, int n_in,
                              void* d_out, int out_size)
{
    const float* x      = (const float*)d_in[0];
    const float* weight = (const float*)d_in[1];
    const float* bias   = (const float*)d_in[2];
    float* out          = (float*)d_out;

    // One warp per row, one row per block: 262144 blocks in row order
    // (sequential DRAM window, single-warp retirement granularity).
    scalar_mapping_kernel<<<TOTAL_ROWS, 32>>>(x, weight, bias, out);
}

// round 8
// speedup vs baseline: 1.1503x; 1.1503x over previous
#include <cuda_runtime.h>

// out[b,c] = dot(x[b,c,:HW], weight[c,:HW]) + bias[c]
// B = 512, C = 512, HW = 784 (float32). HBM-streaming bound.
// R8: R6's winning shape (64-thr CTAs, warp-per-row bursts), but each warp
// processes 2 consecutive rows SEQUENTIALLY: same per-burst quantum, double
// per-warp duty cycle, half the CTA relaunch churn. Block owns 4 consecutive
// rows; grid stays in row order (sequential DRAM window).

#define B_DIM 512
#define C_DIM 512
#define HW_DIM 784
#define HW_VEC4 (HW_DIM / 4)        // 196 float4 per row
#define TOTAL_ROWS (B_DIM * C_DIM)  // 262144

__global__ __launch_bounds__(64) void scalar_mapping_kernel(
    const float* __restrict__ x,
    const float* __restrict__ weight,
    const float* __restrict__ bias,
    float* __restrict__ out)
{
    const int lane = threadIdx.x & 31;
    const int wid  = threadIdx.x >> 5;          // 0 or 1
    const int rbase = blockIdx.x * 4 + wid * 2; // this warp's first row

    #pragma unroll
    for (int rr = 0; rr < 2; ++rr) {
        const int row = rbase + rr;
        const int c   = row & (C_DIM - 1);

        const float4* __restrict__ xr =
            reinterpret_cast<const float4*>(x + (size_t)row * HW_DIM);
        const float4* __restrict__ wr =
            reinterpret_cast<const float4*>(weight + (size_t)c * HW_DIM);

        float sum = 0.0f;

        // 196 float4 per row; 6 full warp-iterations + 1 partial (lanes 0-3).
        #pragma unroll
        for (int i = 0; i < 7; ++i) {
            const int idx = lane + i * 32;
            if (idx < HW_VEC4) {
                const float4 xv = __ldcs(&xr[idx]);  // x streamed once, evict-first
                const float4 wv = __ldg(&wr[idx]);   // weight stays L2-resident
                sum = fmaf(xv.x, wv.x, sum);
                sum = fmaf(xv.y, wv.y, sum);
                sum = fmaf(xv.z, wv.z, sum);
                sum = fmaf(xv.w, wv.w, sum);
            }
        }

        // Warp butterfly reduce
        #pragma unroll
        for (int off = 16; off > 0; off >>= 1)
            sum += __shfl_xor_sync(0xFFFFFFFFu, sum, off);

        if (lane == 0)
            out[row] = sum + __ldg(&bias[c]);
    }
}

extern "C" void kernel_launch(void* const* d_in, const int* in_sizes, int n_in,
                              void* d_out, int out_size)
{
    const float* x      = (const float*)d_in[0];
    const float* weight = (const float*)d_in[1];
    const float* bias   = (const float*)d_in[2];
    float* out          = (float*)d_out;

    // 4 rows per 64-thread block (2 rows per warp, processed sequentially)
    // -> 65536 blocks in row order.
    const int blocks = TOTAL_ROWS / 4;

    scalar_mapping_kernel<<<blocks, 64>>>(x, weight, bias, out);
}

// round 9
// speedup vs baseline: 1.1826x; 1.0281x over previous
#include <cuda_runtime.h>

// out[b,c] = dot(x[b,c,:HW], weight[c,:HW]) + bias[c]
// B = 512, C = 512, HW = 784 (float32). HBM-streaming bound (~828 MB DRAM
// traffic, minimal). R6 shape (64-thr CTAs, one row-burst per warp) = 117.2us
// at DRAM 86%, but regs=34 caps residency below 32 CTAs/SM (69.6K > 64K regs).
// R9 = R6 + __launch_bounds__(64, 32): force regs<=32 so exactly 64 warps/SM
// fit, removing the register-file ceiling on CTA backfill.

#define B_DIM 512
#define C_DIM 512
#define HW_DIM 784
#define HW_VEC4 (HW_DIM / 4)        // 196 float4 per row
#define TOTAL_ROWS (B_DIM * C_DIM)  // 262144

__global__ __launch_bounds__(64, 32) void scalar_mapping_kernel(
    const float* __restrict__ x,
    const float* __restrict__ weight,
    const float* __restrict__ bias,
    float* __restrict__ out)
{
    const int warp = (blockIdx.x * blockDim.x + threadIdx.x) >> 5;  // row = b*C + c
    const int lane = threadIdx.x & 31;

    const int c = warp & (C_DIM - 1);

    const float4* __restrict__ xr =
        reinterpret_cast<const float4*>(x + (size_t)warp * HW_DIM);
    const float4* __restrict__ wr =
        reinterpret_cast<const float4*>(weight + (size_t)c * HW_DIM);

    float sum = 0.0f;

    // 196 float4 per row; 6 full warp-iterations + 1 partial (lanes 0-3).
    #pragma unroll
    for (int i = 0; i < 7; ++i) {
        const int idx = lane + i * 32;
        if (idx < HW_VEC4) {
            const float4 xv = __ldcs(&xr[idx]);  // x streamed once, evict-first
            const float4 wv = __ldg(&wr[idx]);   // weight stays L2-resident
            sum = fmaf(xv.x, wv.x, sum);
            sum = fmaf(xv.y, wv.y, sum);
            sum = fmaf(xv.z, wv.z, sum);
            sum = fmaf(xv.w, wv.w, sum);
        }
    }

    // Warp butterfly reduce
    #pragma unroll
    for (int off = 16; off > 0; off >>= 1)
        sum += __shfl_xor_sync(0xFFFFFFFFu, sum, off);

    if (lane == 0)
        out[warp] = sum + __ldg(&bias[c]);
}

extern "C" void kernel_launch(void* const* d_in, const int* in_sizes, int n_in,
                              void* d_out, int out_size)
{
    const float* x      = (const float*)d_in[0];
    const float* weight = (const float*)d_in[1];
    const float* bias   = (const float*)d_in[2];
    float* out          = (float*)d_out;

    // One warp per row; 2 warps per 64-thread block -> 131072 blocks in row
    // order (sequential DRAM window, fine retirement granularity, full RF fit).
    const int blocks = TOTAL_ROWS / 2;

    scalar_mapping_kernel<<<blocks, 64>>>(x, weight, bias, out);
}

// round 10
// speedup vs baseline: 1.1894x; 1.0058x over previous
#include <cuda_runtime.h>

// out[b,c] = dot(x[b,c,:HW], weight[c,:HW]) + bias[c]
// B = 512, C = 512, HW = 784 (float32). HBM-streaming bound, traffic minimal.
// R10: two-row aligned cooperative blocks. One row = 3136 B = 24.5 cache
// lines (odd rows start mid-line); a 2-row pair = 6272 B = exactly 49 lines.
// Each 64-thread block streams its pair as one contiguous, 128B-aligned
// window (392 float4), routing each float4's FMA to the correct weight row.

#define B_DIM 512
#define C_DIM 512
#define HW_DIM 784
#define HW_VEC4 (HW_DIM / 4)          // 196 float4 per row
#define PAIR_VEC4 (2 * HW_VEC4)       // 392 float4 per row-pair
#define TOTAL_ROWS (B_DIM * C_DIM)    // 262144

__global__ __launch_bounds__(64, 32) void scalar_mapping_kernel(
    const float* __restrict__ x,
    const float* __restrict__ weight,
    const float* __restrict__ bias,
    float* __restrict__ out)
{
    __shared__ float part[4];   // {w0.s0, w0.s1, w1.s0, w1.s1}

    const int tid  = threadIdx.x;        // 0..63
    const int lane = tid & 31;
    const int wid  = tid >> 5;           // 0 or 1

    const int r0 = blockIdx.x * 2;       // even row
    const int r1 = r0 + 1;
    const int c0 = r0 & (C_DIM - 1);     // even, so c1 = c0+1 never wraps
    const int c1 = c0 + 1;

    // Contiguous, 128B-aligned 2-row window of x.
    const float4* __restrict__ xr =
        reinterpret_cast<const float4*>(x + (size_t)r0 * HW_DIM);
    const float4* __restrict__ w0 =
        reinterpret_cast<const float4*>(weight + (size_t)c0 * HW_DIM);
    const float4* __restrict__ w1 =
        reinterpret_cast<const float4*>(weight + (size_t)c1 * HW_DIM);

    float s0 = 0.0f, s1 = 0.0f;

    // 392 float4 over 64 threads: 6 full iterations + partial (tid < 8).
    #pragma unroll
    for (int i = 0; i < 7; ++i) {
        const int f = tid + i * 64;
        if (f < PAIR_VEC4) {
            const float4 xv = __ldcs(&xr[f]);   // aligned DRAM stream
            if (f < HW_VEC4) {
                const float4 wv = __ldg(&w0[f]);
                s0 = fmaf(xv.x, wv.x, s0);
                s0 = fmaf(xv.y, wv.y, s0);
                s0 = fmaf(xv.z, wv.z, s0);
                s0 = fmaf(xv.w, wv.w, s0);
            } else {
                const float4 wv = __ldg(&w1[f - HW_VEC4]);
                s1 = fmaf(xv.x, wv.x, s1);
                s1 = fmaf(xv.y, wv.y, s1);
                s1 = fmaf(xv.z, wv.z, s1);
                s1 = fmaf(xv.w, wv.w, s1);
            }
        }
    }

    // Warp-level butterfly reduce of both accumulators.
    #pragma unroll
    for (int off = 16; off > 0; off >>= 1) {
        s0 += __shfl_xor_sync(0xFFFFFFFFu, s0, off);
        s1 += __shfl_xor_sync(0xFFFFFFFFu, s1, off);
    }

    if (lane == 0) {
        part[wid * 2 + 0] = s0;
        part[wid * 2 + 1] = s1;
    }
    __syncthreads();

    if (tid == 0)
        out[r0] = part[0] + part[2] + __ldg(&bias[c0]);
    else if (tid == 1)
        out[r1] = part[1] + part[3] + __ldg(&bias[c1]);
}

extern "C" void kernel_launch(void* const* d_in, const int* in_sizes, int n_in,
                              void* d_out, int out_size)
{
    const float* x      = (const float*)d_in[0];
    const float* weight = (const float*)d_in[1];
    const float* bias   = (const float*)d_in[2];
    float* out          = (float*)d_out;

    // One 2-row pair per 64-thread block -> 131072 blocks in row order.
    const int blocks = TOTAL_ROWS / 2;

    scalar_mapping_kernel<<<blocks, 64>>>(x, weight, bias, out);
}